// round 2
// baseline (speedup 1.0000x reference)
#include <cuda_runtime.h>

// End2End_7645041787474 — fused forward collapse, chunked argmax version.
//
// Math (see R1): forward value of g is one_hot(argmax(logits+gumbel));
// every output row is exactly one W row (or zero); nn_idx is that row's
// own index (or 0). Only real traffic: (logits+gumbel) rows where
// rwrt_attention==1 (~131 MB).
//
// R2 change: each row's 32128-wide argmax is split across 4 CTAs (column
// chunks) combining via atomicMax on a packed u64 key:
//   key = monotone(float) << 32 | ~index
// so max(key) == (max value, lowest index on ties) — exact jnp.argmax.

namespace {
constexpr int Bc  = 8;
constexpr int Lc  = 128;
constexpr int VFc = 32128;
constexpr int Vc  = 32100;
constexpr int Dc  = 768;
constexpr int NROWS = Bc * Lc;        // 1024
constexpr int NT  = 256;
constexpr int CHUNKS = 4;
constexpr int N4  = VFc / 4;          // 8032 float4 per row
constexpr int CPC = (N4 + CHUNKS - 1) / CHUNKS;  // 2008 float4 per chunk
}

__device__ unsigned long long g_scr[NROWS];
__device__ int g_len[Bc];

__device__ __forceinline__ unsigned long long pack_key(float v, int idx) {
    unsigned u = __float_as_uint(v);
    u = (u & 0x80000000u) ? ~u : (u | 0x80000000u);   // monotone float -> u32
    return ((unsigned long long)u << 32) | (unsigned)(~(unsigned)idx);
}

// ---- kernel 1: zero scratch + compute len[b] = sum(rwrt[b,:]) ----
__global__ void init_kernel(const int* __restrict__ rwrt) {
    const int tid = threadIdx.x;                       // 256 threads, 1 block
    #pragma unroll
    for (int i = 0; i < NROWS / NT; i++)
        g_scr[tid + i * NT] = 0ULL;

    const int w = tid >> 5, lane = tid & 31;           // warp w handles batch w
    int s = 0;
    #pragma unroll
    for (int i = 0; i < Lc / 32; i++)
        s += rwrt[w * Lc + lane + i * 32];
    #pragma unroll
    for (int off = 16; off > 0; off >>= 1)
        s += __shfl_down_sync(0xffffffffu, s, off);
    if (lane == 0) g_len[w] = s;
}

// ---- kernel 2: per-(row,chunk) partial argmax -> atomicMax ----
__global__ __launch_bounds__(NT)
void argmax_kernel(const float* __restrict__ logits,
                   const float* __restrict__ gumbel,
                   const int*   __restrict__ rwrt)
{
    const int row   = blockIdx.x >> 2;    // CHUNKS = 4
    const int chunk = blockIdx.x & 3;
    if (!rwrt[row]) return;

    const int tid = threadIdx.x;
    const int j0  = chunk * CPC;
    const int j1  = (j0 + CPC < N4) ? (j0 + CPC) : N4;

    const float4* lp = reinterpret_cast<const float4*>(logits + (size_t)row * VFc);
    const float4* gp = reinterpret_cast<const float4*>(gumbel + (size_t)row * VFc);

    float bestv = -3.402823466e38f;
    int   besti = 0x7fffffff;
    #pragma unroll 4
    for (int j = j0 + tid; j < j1; j += NT) {
        const float4 a = lp[j];
        const float4 c = gp[j];
        const float z0 = a.x + c.x;
        const float z1 = a.y + c.y;
        const float z2 = a.z + c.z;
        const float z3 = a.w + c.w;
        const int base = j << 2;
        // strict '>' within ascending scan keeps lowest index per thread
        if (z0 > bestv) { bestv = z0; besti = base;     }
        if (z1 > bestv) { bestv = z1; besti = base + 1; }
        if (z2 > bestv) { bestv = z2; besti = base + 2; }
        if (z3 > bestv) { bestv = z3; besti = base + 3; }
    }

    unsigned long long key = pack_key(bestv, besti);

    // warp reduce (max of packed key preserves value+tiebreak semantics)
    #pragma unroll
    for (int off = 16; off > 0; off >>= 1) {
        unsigned long long o = __shfl_down_sync(0xffffffffu, key, off);
        if (o > key) key = o;
    }
    __shared__ unsigned long long s_key[NT / 32];
    if ((tid & 31) == 0) s_key[tid >> 5] = key;
    __syncthreads();
    if (tid == 0) {
        #pragma unroll
        for (int w = 1; w < NT / 32; w++)
            if (s_key[w] > key) key = s_key[w];
        atomicMax(&g_scr[row], key);
    }
}

// ---- kernel 3: decode + gather W row + write embeds / nn_idx ----
__global__ __launch_bounds__(NT)
void write_kernel(const float* __restrict__ wemb,
                  const int*   __restrict__ rwrt,
                  const int*   __restrict__ psg,
                  float*       __restrict__ out)
{
    const int row = blockIdx.x;
    const int b   = row >> 7;
    const int l   = row & 127;
    const int tid = threadIdx.x;

    int src, nn;
    if (rwrt[row]) {
        const unsigned long long key = g_scr[row];
        const int g = (int)(~(unsigned)(key & 0xffffffffu));
        src = (g < Vc) ? g : -1;   // g >= V -> zero row (g[..., :V] truncation)
        nn  = (g < Vc) ? g : 0;    // zero row -> sims all 0 -> argmax 0
    } else {
        const int len = g_len[b];
        const int idx = psg[b * Lc + (l - len)];
        src = idx;
        nn  = idx;
    }

    float4* orow = reinterpret_cast<float4*>(out + (size_t)row * Dc);
    if (tid < Dc / 4) {            // 192 float4s
        if (src >= 0) {
            const float4* wrow = reinterpret_cast<const float4*>(wemb + (size_t)src * Dc);
            orow[tid] = wrow[tid];
        } else {
            orow[tid] = make_float4(0.f, 0.f, 0.f, 0.f);
        }
    }
    if (tid == 0)
        out[(size_t)NROWS * Dc + row] = (float)nn;
}

extern "C" void kernel_launch(void* const* d_in, const int* in_sizes, int n_in,
                              void* d_out, int out_size) {
    const float* logits = (const float*)d_in[0];
    const float* gumbel = (const float*)d_in[1];
    const float* wemb   = (const float*)d_in[2];
    const int*   rwrt   = (const int*)d_in[3];
    const int*   psg    = (const int*)d_in[4];
    float*       out    = (float*)d_out;

    init_kernel<<<1, NT>>>(rwrt);
    argmax_kernel<<<NROWS * CHUNKS, NT>>>(logits, gumbel, rwrt);
    write_kernel<<<NROWS, NT>>>(wemb, rwrt, psg, out);
}